// round 15
// baseline (speedup 1.0000x reference)
#include <cuda_runtime.h>
#include <stdint.h>

#define N_MAX 100000
#define E_MAX 800000

// Scratch (device globals; no allocation allowed in kernel_launch)
__device__ float g_bufA[(size_t)N_MAX * 64];
__device__ float g_bufB[(size_t)N_MAX * 64];
__device__ float g_h3[(size_t)N_MAX * 7];
__device__ float g_dinv[N_MAX];
__device__ int   g_deg[N_MAX];
__device__ int   g_ptr[N_MAX];
__device__ int   g_fill[N_MAX];
__device__ int   g_csr[E_MAX];
__device__ int   g_blockSums[512];

// ---------------------------------------------------------------------------
// degree (zeroing done by cudaMemsetAsync in kernel_launch)
// ---------------------------------------------------------------------------
__global__ void k_count_deg(const int* __restrict__ ei, int nE) {
    int e = blockIdx.x * blockDim.x + threadIdx.x;
    if (e < nE) atomicAdd(&g_deg[ei[nE + e]], 1);
}

// ---------------------------------------------------------------------------
// CSR build
// ---------------------------------------------------------------------------
__global__ void k_scanA(int n) {
    __shared__ int sh[256];
    int i = blockIdx.x * 256 + threadIdx.x;
    int t = threadIdx.x;
    sh[t] = (i < n) ? g_deg[i] : 0;
    __syncthreads();
    for (int s = 128; s > 0; s >>= 1) {
        if (t < s) sh[t] += sh[t + s];
        __syncthreads();
    }
    if (t == 0) g_blockSums[blockIdx.x] = sh[0];
}

__global__ void k_scanC(int n) {
    __shared__ int sh[256];
    __shared__ int blockOff;
    int i = blockIdx.x * 256 + threadIdx.x;
    int t = threadIdx.x;

    int partial = 0;
    for (int j = t; j < blockIdx.x; j += 256) partial += g_blockSums[j];
    sh[t] = partial;
    __syncthreads();
    for (int s = 128; s > 0; s >>= 1) {
        if (t < s) sh[t] += sh[t + s];
        __syncthreads();
    }
    if (t == 0) blockOff = sh[0];
    __syncthreads();

    int v = (i < n) ? g_deg[i] : 0;
    sh[t] = v;
    __syncthreads();
    for (int off = 1; off < 256; off <<= 1) {
        int x = (t >= off) ? sh[t - off] : 0;
        __syncthreads();
        sh[t] += x;
        __syncthreads();
    }
    if (i < n) {
        int excl = sh[t] - v + blockOff;
        g_ptr[i]  = excl;
        g_fill[i] = excl;
        g_dinv[i] = rsqrtf((float)v + 1.0f);
    }
}

__global__ void k_fill(const int* __restrict__ ei, int nE) {
    int e = blockIdx.x * blockDim.x + threadIdx.x;
    if (e < nE) {
        int s = ei[e];
        int d = ei[nE + e];
        int pos = atomicAdd(&g_fill[d], 1);
        g_csr[pos] = s;
    }
}

// ---------------------------------------------------------------------------
// f32x2 helpers
// ---------------------------------------------------------------------------
__device__ __forceinline__ unsigned long long pack_dup(float v) {
    unsigned long long r;
    asm("mov.b64 %0, {%1, %1};" : "=l"(r) : "f"(v));
    return r;
}
__device__ __forceinline__ void ffma2(unsigned long long& acc,
                                      unsigned long long a,
                                      unsigned long long b) {
    asm("fma.rn.f32x2 %0, %1, %2, %0;" : "+l"(acc) : "l"(a), "l"(b));
}

// ---------------------------------------------------------------------------
// GEMM: [n x K] @ [K x 64] -> h_out.  64x64 block tile, 256 threads,
// thread tile 2 rows x 8 cols (fewer non-FFMA issue slots per kk).
// Staging + XOR swizzle identical to the proven R13 kernel.
// ---------------------------------------------------------------------------
template <int K, bool RELU>
__global__ void __launch_bounds__(256) k_gemm64(
    const float* __restrict__ in, const float* __restrict__ W,
    float* __restrict__ h_out, int n)
{
    constexpr int KC = 32;
    __shared__ float xs[KC][72];
    __shared__ float ws[KC][64];

    int tid = threadIdx.x;
    int tx = tid & 7, ty = tid >> 3;
    int rowBase = blockIdx.x * 64;
    int r0 = ty * 2, c0 = tx * 8;

    unsigned long long acc2[2][4];
#pragma unroll
    for (int i = 0; i < 2; i++)
#pragma unroll
        for (int j = 0; j < 4; j++) acc2[i][j] = 0ull;

    int lr = tid >> 2;
    int lk = (tid & 3) * 8;

    for (int k0 = 0; k0 < K; k0 += KC) {
        {
            int grow = rowBase + lr;
            float4 v0, v1;
            if (grow < n) {
                const float* p = in + (size_t)grow * K + k0 + lk;
                v0 = *(const float4*)p;
                v1 = *(const float4*)(p + 4);
            } else {
                v0 = make_float4(0.f, 0.f, 0.f, 0.f);
                v1 = v0;
            }
            if (RELU) {
                v0.x = fmaxf(v0.x, 0.f); v0.y = fmaxf(v0.y, 0.f);
                v0.z = fmaxf(v0.z, 0.f); v0.w = fmaxf(v0.w, 0.f);
                v1.x = fmaxf(v1.x, 0.f); v1.y = fmaxf(v1.y, 0.f);
                v1.z = fmaxf(v1.z, 0.f); v1.w = fmaxf(v1.w, 0.f);
            }
            xs[lk + 0][lr ^ ((lk + 0) & 24)] = v0.x;
            xs[lk + 1][lr ^ ((lk + 1) & 24)] = v0.y;
            xs[lk + 2][lr ^ ((lk + 2) & 24)] = v0.z;
            xs[lk + 3][lr ^ ((lk + 3) & 24)] = v0.w;
            xs[lk + 4][lr ^ ((lk + 4) & 24)] = v1.x;
            xs[lk + 5][lr ^ ((lk + 5) & 24)] = v1.y;
            xs[lk + 6][lr ^ ((lk + 6) & 24)] = v1.z;
            xs[lk + 7][lr ^ ((lk + 7) & 24)] = v1.w;
        }
        {
            int lkk = tid >> 3;
            int lc  = (tid & 7) * 8;
            const float* p = W + (size_t)(k0 + lkk) * 64 + lc;
            float4 w0 = *(const float4*)p;
            float4 w1 = *(const float4*)(p + 4);
            *(float4*)&ws[lkk][lc]     = w0;
            *(float4*)&ws[lkk][lc + 4] = w1;
        }
        __syncthreads();
#pragma unroll
        for (int kk = 0; kk < KC; kk++) {
            // x: 2 rows (r0 even; swizzle bits >=3 so adjacency preserved)
            float2 xv = *(const float2*)&xs[kk][r0 ^ (kk & 24)];
            const unsigned long long* wp =
                (const unsigned long long*)&ws[kk][c0];
            unsigned long long w0 = wp[0], w1 = wp[1];
            unsigned long long w2 = wp[2], w3 = wp[3];
            unsigned long long x0 = pack_dup(xv.x);
            unsigned long long x1 = pack_dup(xv.y);
            ffma2(acc2[0][0], x0, w0); ffma2(acc2[0][1], x0, w1);
            ffma2(acc2[0][2], x0, w2); ffma2(acc2[0][3], x0, w3);
            ffma2(acc2[1][0], x1, w0); ffma2(acc2[1][1], x1, w1);
            ffma2(acc2[1][2], x1, w2); ffma2(acc2[1][3], x1, w3);
        }
        __syncthreads();
    }

#pragma unroll
    for (int i = 0; i < 2; i++) {
        int grow = rowBase + r0 + i;
        if (grow < n) {
            float* dst = h_out + (size_t)grow * 64 + c0;
#pragma unroll
            for (int q = 0; q < 2; q++) {
                float4 hv;
                hv.x = __uint_as_float((unsigned)(acc2[i][2*q+0] & 0xffffffffull));
                hv.y = __uint_as_float((unsigned)(acc2[i][2*q+0] >> 32));
                hv.z = __uint_as_float((unsigned)(acc2[i][2*q+1] & 0xffffffffull));
                hv.w = __uint_as_float((unsigned)(acc2[i][2*q+1] >> 32));
                *(float4*)(dst + q * 4) = hv;
            }
        }
    }
}

// ---------------------------------------------------------------------------
// CSR pull aggregation (64-wide): TWO nodes per warp (16-lane groups,
// float4 per lane). Doubles per-warp MLP; LDG.128 gathers.
// out[d] = b + h[d]*dinv[d]^2 + sum_{s in N(d)} h[s]*dinv[s]*dinv[d]
// ---------------------------------------------------------------------------
__global__ void __launch_bounds__(256) k_agg64_csr(
    const float* __restrict__ h, const float* __restrict__ b,
    float* __restrict__ out, int n)
{
    int gid   = blockIdx.x * 256 + threadIdx.x;
    int node  = gid >> 4;            // one node per 16-lane group
    int glane = threadIdx.x & 15;
    if (node >= n) return;
    int d = node;

    float dd = g_dinv[d];
    int start = g_ptr[d];
    int deg   = g_deg[d];

    float4 hv = *(const float4*)(h + (size_t)d * 64 + glane * 4);
    float d2 = dd * dd;
    float4 bb = *(const float4*)(b + glane * 4);
    float4 acc;
    acc.x = fmaf(hv.x, d2, bb.x);
    acc.y = fmaf(hv.y, d2, bb.y);
    acc.z = fmaf(hv.z, d2, bb.z);
    acc.w = fmaf(hv.w, d2, bb.w);

    for (int base = 0; base < deg; base += 16) {
        int cnt = min(16, deg - base);
        int s = 0; float w = 0.f;
        if (glane < cnt) {
            s = g_csr[start + base + glane];
            w = g_dinv[s];
        }
#pragma unroll 4
        for (int j = 0; j < cnt; j++) {
            int   sj = __shfl_sync(0xffffffffu, s, j, 16);
            float wj = __shfl_sync(0xffffffffu, w, j, 16);
            float coef = wj * dd;
            float4 hs = *(const float4*)(h + (size_t)sj * 64 + glane * 4);
            acc.x = fmaf(hs.x, coef, acc.x);
            acc.y = fmaf(hs.y, coef, acc.y);
            acc.z = fmaf(hs.z, coef, acc.z);
            acc.w = fmaf(hs.w, coef, acc.w);
        }
    }
    *(float4*)(out + (size_t)d * 64 + glane * 4) = acc;
}

// ---------------------------------------------------------------------------
// Layer 3 GEMM: relu(in[n x 64]) @ W3[64 x 7] -> h3 only
// ---------------------------------------------------------------------------
__global__ void __launch_bounds__(256) k_gemm7(
    const float* __restrict__ in, const float* __restrict__ W,
    float* __restrict__ h_out, int n)
{
    __shared__ float wsh[64 * 7];
    int tid = threadIdx.x;
    for (int i = tid; i < 448; i += 256) wsh[i] = W[i];
    __syncthreads();

    int row = blockIdx.x * blockDim.x + tid;
    if (row >= n) return;

    float acc[7];
#pragma unroll
    for (int c = 0; c < 7; c++) acc[c] = 0.f;

    const float* p = in + (size_t)row * 64;
#pragma unroll
    for (int k = 0; k < 64; k += 4) {
        float4 v = *(const float4*)(p + k);
        v.x = fmaxf(v.x, 0.f); v.y = fmaxf(v.y, 0.f);
        v.z = fmaxf(v.z, 0.f); v.w = fmaxf(v.w, 0.f);
#pragma unroll
        for (int c = 0; c < 7; c++) {
            acc[c] = fmaf(v.x, wsh[(k + 0) * 7 + c], acc[c]);
            acc[c] = fmaf(v.y, wsh[(k + 1) * 7 + c], acc[c]);
            acc[c] = fmaf(v.z, wsh[(k + 2) * 7 + c], acc[c]);
            acc[c] = fmaf(v.w, wsh[(k + 3) * 7 + c], acc[c]);
        }
    }
#pragma unroll
    for (int c = 0; c < 7; c++)
        h_out[(size_t)row * 7 + c] = acc[c];
}

// ---------------------------------------------------------------------------
// CSR pull aggregation (7-wide)
// ---------------------------------------------------------------------------
__global__ void __launch_bounds__(256) k_agg7_csr(
    const float* __restrict__ h, const float* __restrict__ b,
    float* __restrict__ out, int n)
{
    int warp = (blockIdx.x * 256 + threadIdx.x) >> 5;
    int lane = threadIdx.x & 31;
    if (warp >= n) return;
    int d = warp;

    float dd = g_dinv[d];
    int start = g_ptr[d];
    int deg   = g_deg[d];

    float acc = 0.f;
    if (lane < 7)
        acc = fmaf(h[(size_t)d * 7 + lane], dd * dd, b[lane]);

    for (int base = 0; base < deg; base += 32) {
        int cnt = min(32, deg - base);
        int s = 0; float w = 0.f;
        if (lane < cnt) {
            s = g_csr[start + base + lane];
            w = g_dinv[s];
        }
        for (int j = 0; j < cnt; j++) {
            int   sj = __shfl_sync(0xffffffffu, s, j);
            float wj = __shfl_sync(0xffffffffu, w, j);
            if (lane < 7)
                acc = fmaf(h[(size_t)sj * 7 + lane], wj * dd, acc);
        }
    }
    if (lane < 7)
        out[(size_t)d * 7 + lane] = acc;
}

// ---------------------------------------------------------------------------
// launch — CSR build (default stream) overlapped with gemm1 (side stream)
// ---------------------------------------------------------------------------
extern "C" void kernel_launch(void* const* d_in, const int* in_sizes, int n_in,
                              void* d_out, int out_size)
{
    const float* x  = (const float*)d_in[0];
    const int*   ei = (const int*)d_in[1];
    const float* W1 = (const float*)d_in[2];
    const float* b1 = (const float*)d_in[3];
    const float* W2 = (const float*)d_in[4];
    const float* b2 = (const float*)d_in[5];
    const float* W3 = (const float*)d_in[6];
    const float* b3 = (const float*)d_in[7];

    int n  = in_sizes[0] / 128;
    int nE = in_sizes[1] / 2;
    float* out = (float*)d_out;

    float *bufA, *bufB, *h3;
    int* degp;
    cudaGetSymbolAddress((void**)&bufA, g_bufA);
    cudaGetSymbolAddress((void**)&bufB, g_bufB);
    cudaGetSymbolAddress((void**)&h3,   g_h3);
    cudaGetSymbolAddress((void**)&degp, g_deg);

    static cudaStream_t s2 = nullptr;
    static cudaEvent_t evFork = nullptr, evJoin = nullptr;
    if (!s2) {
        cudaStreamCreateWithFlags(&s2, cudaStreamNonBlocking);
        cudaEventCreateWithFlags(&evFork, cudaEventDisableTiming);
        cudaEventCreateWithFlags(&evJoin, cudaEventDisableTiming);
    }

    int nb_n  = (n + 255) / 256;
    int nb_e  = (nE + 255) / 256;
    int nb_g  = (n + 63) / 64;
    int nb_g16 = (int)(((long long)n * 16 + 255) / 256);   // 16 lanes/node
    int nb_w  = (int)(((long long)n * 32 + 255) / 256);    // 32 lanes/node

    // fork: gemm1 on side stream (depends only on x, W1)
    cudaEventRecord(evFork, 0);
    cudaStreamWaitEvent(s2, evFork, 0);
    k_gemm64<128, false><<<nb_g, 256, 0, s2>>>(x, W1, bufA, n);
    cudaEventRecord(evJoin, s2);

    // CSR build on default stream (runs concurrently with gemm1)
    cudaMemsetAsync(degp, 0, (size_t)n * sizeof(int));
    k_count_deg<<<nb_e, 256>>>(ei, nE);
    k_scanA<<<nb_n, 256>>>(n);
    k_scanC<<<nb_n, 256>>>(n);
    k_fill<<<nb_e, 256>>>(ei, nE);

    // join: agg1 needs CSR (stream order) + gemm1 (event)
    cudaStreamWaitEvent(0, evJoin, 0);
    k_agg64_csr<<<nb_g16, 256>>>(bufA, b1, bufB, n);

    // layer 2
    k_gemm64<64, true><<<nb_g, 256>>>(bufB, W2, bufA, n);
    k_agg64_csr<<<nb_g16, 256>>>(bufA, b2, bufB, n);

    // layer 3
    k_gemm7<<<nb_n, 256>>>(bufB, W3, h3, n);
    k_agg7_csr<<<nb_w, 256>>>(h3, b3, out, n);
}

// round 16
// speedup vs baseline: 1.4988x; 1.4988x over previous
#include <cuda_runtime.h>
#include <stdint.h>

#define N_MAX 100000
#define E_MAX 800000

// Scratch (device globals; no allocation allowed in kernel_launch)
__device__ float g_bufA[(size_t)N_MAX * 64];
__device__ float g_bufB[(size_t)N_MAX * 64];
__device__ float g_h3[(size_t)N_MAX * 7];
__device__ float g_dinv[N_MAX];
__device__ int   g_deg[N_MAX];
__device__ int   g_ptr[N_MAX];
__device__ int   g_fill[N_MAX];
__device__ int   g_csr[E_MAX];
__device__ int   g_blockSums[512];

// ---------------------------------------------------------------------------
// degree (zeroing done by cudaMemsetAsync in kernel_launch)
// ---------------------------------------------------------------------------
__global__ void k_count_deg(const int* __restrict__ ei, int nE) {
    int e = blockIdx.x * blockDim.x + threadIdx.x;
    if (e < nE) atomicAdd(&g_deg[ei[nE + e]], 1);
}

// ---------------------------------------------------------------------------
// CSR build
// ---------------------------------------------------------------------------
__global__ void k_scanA(int n) {
    __shared__ int sh[256];
    int i = blockIdx.x * 256 + threadIdx.x;
    int t = threadIdx.x;
    sh[t] = (i < n) ? g_deg[i] : 0;
    __syncthreads();
    for (int s = 128; s > 0; s >>= 1) {
        if (t < s) sh[t] += sh[t + s];
        __syncthreads();
    }
    if (t == 0) g_blockSums[blockIdx.x] = sh[0];
}

__global__ void k_scanC(int n) {
    __shared__ int sh[256];
    __shared__ int blockOff;
    int i = blockIdx.x * 256 + threadIdx.x;
    int t = threadIdx.x;

    int partial = 0;
    for (int j = t; j < blockIdx.x; j += 256) partial += g_blockSums[j];
    sh[t] = partial;
    __syncthreads();
    for (int s = 128; s > 0; s >>= 1) {
        if (t < s) sh[t] += sh[t + s];
        __syncthreads();
    }
    if (t == 0) blockOff = sh[0];
    __syncthreads();

    int v = (i < n) ? g_deg[i] : 0;
    sh[t] = v;
    __syncthreads();
    for (int off = 1; off < 256; off <<= 1) {
        int x = (t >= off) ? sh[t - off] : 0;
        __syncthreads();
        sh[t] += x;
        __syncthreads();
    }
    if (i < n) {
        int excl = sh[t] - v + blockOff;
        g_ptr[i]  = excl;
        g_fill[i] = excl;
        g_dinv[i] = rsqrtf((float)v + 1.0f);
    }
}

__global__ void k_fill(const int* __restrict__ ei, int nE) {
    int e = blockIdx.x * blockDim.x + threadIdx.x;
    if (e < nE) {
        int s = ei[e];
        int d = ei[nE + e];
        int pos = atomicAdd(&g_fill[d], 1);
        g_csr[pos] = s;
    }
}

// ---------------------------------------------------------------------------
// f32x2 helpers
// ---------------------------------------------------------------------------
__device__ __forceinline__ unsigned long long pack_dup(float v) {
    unsigned long long r;
    asm("mov.b64 %0, {%1, %1};" : "=l"(r) : "f"(v));
    return r;
}
__device__ __forceinline__ void ffma2(unsigned long long& acc,
                                      unsigned long long a,
                                      unsigned long long b) {
    asm("fma.rn.f32x2 %0, %1, %2, %0;" : "+l"(acc) : "l"(a), "l"(b));
}

// ---------------------------------------------------------------------------
// GEMM (R8 shape + xs XOR swizzle, 192us-proven): [n x K] @ [K x 64]
// ---------------------------------------------------------------------------
template <int K, bool RELU>
__global__ void __launch_bounds__(256) k_gemm64(
    const float* __restrict__ in, const float* __restrict__ W,
    float* __restrict__ h_out, int n)
{
    constexpr int KC = 32;
    __shared__ float xs[KC][72];
    __shared__ float ws[KC][64];

    int tid = threadIdx.x;
    int tx = tid & 15, ty = tid >> 4;
    int rowBase = blockIdx.x * 64;
    int r0 = ty * 4, c0 = tx * 4;

    unsigned long long acc2[4][2];
#pragma unroll
    for (int i = 0; i < 4; i++) { acc2[i][0] = 0ull; acc2[i][1] = 0ull; }

    int lr = tid >> 2;
    int lk = (tid & 3) * 8;

    for (int k0 = 0; k0 < K; k0 += KC) {
        {
            int grow = rowBase + lr;
            float4 v0, v1;
            if (grow < n) {
                const float* p = in + (size_t)grow * K + k0 + lk;
                v0 = *(const float4*)p;
                v1 = *(const float4*)(p + 4);
            } else {
                v0 = make_float4(0.f, 0.f, 0.f, 0.f);
                v1 = v0;
            }
            if (RELU) {
                v0.x = fmaxf(v0.x, 0.f); v0.y = fmaxf(v0.y, 0.f);
                v0.z = fmaxf(v0.z, 0.f); v0.w = fmaxf(v0.w, 0.f);
                v1.x = fmaxf(v1.x, 0.f); v1.y = fmaxf(v1.y, 0.f);
                v1.z = fmaxf(v1.z, 0.f); v1.w = fmaxf(v1.w, 0.f);
            }
            xs[lk + 0][lr ^ ((lk + 0) & 24)] = v0.x;
            xs[lk + 1][lr ^ ((lk + 1) & 24)] = v0.y;
            xs[lk + 2][lr ^ ((lk + 2) & 24)] = v0.z;
            xs[lk + 3][lr ^ ((lk + 3) & 24)] = v0.w;
            xs[lk + 4][lr ^ ((lk + 4) & 24)] = v1.x;
            xs[lk + 5][lr ^ ((lk + 5) & 24)] = v1.y;
            xs[lk + 6][lr ^ ((lk + 6) & 24)] = v1.z;
            xs[lk + 7][lr ^ ((lk + 7) & 24)] = v1.w;
        }
        {
            int lkk = tid >> 3;
            int lc  = (tid & 7) * 8;
            const float* p = W + (size_t)(k0 + lkk) * 64 + lc;
            float4 w0 = *(const float4*)p;
            float4 w1 = *(const float4*)(p + 4);
            *(float4*)&ws[lkk][lc]     = w0;
            *(float4*)&ws[lkk][lc + 4] = w1;
        }
        __syncthreads();
#pragma unroll
        for (int kk = 0; kk < KC; kk++) {
            float4 xv = *(const float4*)&xs[kk][r0 ^ (kk & 24)];
            const unsigned long long* wp =
                (const unsigned long long*)&ws[kk][c0];
            unsigned long long w0 = wp[0], w1 = wp[1];
            unsigned long long x0 = pack_dup(xv.x);
            unsigned long long x1 = pack_dup(xv.y);
            unsigned long long x2 = pack_dup(xv.z);
            unsigned long long x3 = pack_dup(xv.w);
            ffma2(acc2[0][0], x0, w0); ffma2(acc2[0][1], x0, w1);
            ffma2(acc2[1][0], x1, w0); ffma2(acc2[1][1], x1, w1);
            ffma2(acc2[2][0], x2, w0); ffma2(acc2[2][1], x2, w1);
            ffma2(acc2[3][0], x3, w0); ffma2(acc2[3][1], x3, w1);
        }
        __syncthreads();
    }

#pragma unroll
    for (int i = 0; i < 4; i++) {
        int grow = rowBase + r0 + i;
        if (grow < n) {
            float4 hv;
            hv.x = __uint_as_float((unsigned)(acc2[i][0] & 0xffffffffull));
            hv.y = __uint_as_float((unsigned)(acc2[i][0] >> 32));
            hv.z = __uint_as_float((unsigned)(acc2[i][1] & 0xffffffffull));
            hv.w = __uint_as_float((unsigned)(acc2[i][1] >> 32));
            *(float4*)&h_out[(size_t)grow * 64 + c0] = hv;
        }
    }
}

// ---------------------------------------------------------------------------
// CSR pull aggregation (64-wide): one warp per dst node (warp-uniform loop),
// TWO neighbors per inner iteration for 2x memory-level parallelism.
// out[d] = b + h[d]*dinv[d]^2 + sum_{s in N(d)} h[s]*dinv[s]*dinv[d]
// ---------------------------------------------------------------------------
__global__ void __launch_bounds__(256) k_agg64_csr(
    const float* __restrict__ h, const float* __restrict__ b,
    float* __restrict__ out, int n)
{
    int warp = (blockIdx.x * 256 + threadIdx.x) >> 5;
    int lane = threadIdx.x & 31;
    if (warp >= n) return;
    int d = warp;

    float dd = g_dinv[d];
    int start = g_ptr[d];
    int deg   = g_deg[d];

    float2 hv = *(const float2*)(h + (size_t)d * 64 + lane * 2);
    float d2 = dd * dd;
    float2 acc;
    acc.x = fmaf(hv.x, d2, b[lane * 2]);
    acc.y = fmaf(hv.y, d2, b[lane * 2 + 1]);

    for (int base = 0; base < deg; base += 32) {
        int cnt = min(32, deg - base);
        int s = 0; float w = 0.f;
        if (lane < cnt) {
            s = g_csr[start + base + lane];
            w = g_dinv[s];
        }
        int j = 0;
#pragma unroll 2
        for (; j + 1 < cnt; j += 2) {
            int   sj0 = __shfl_sync(0xffffffffu, s, j);
            int   sj1 = __shfl_sync(0xffffffffu, s, j + 1);
            float wj0 = __shfl_sync(0xffffffffu, w, j);
            float wj1 = __shfl_sync(0xffffffffu, w, j + 1);
            float c0 = wj0 * dd;
            float c1 = wj1 * dd;
            float2 h0 = *(const float2*)(h + (size_t)sj0 * 64 + lane * 2);
            float2 h1 = *(const float2*)(h + (size_t)sj1 * 64 + lane * 2);
            acc.x = fmaf(h0.x, c0, acc.x);
            acc.y = fmaf(h0.y, c0, acc.y);
            acc.x = fmaf(h1.x, c1, acc.x);
            acc.y = fmaf(h1.y, c1, acc.y);
        }
        if (j < cnt) {
            int   sj = __shfl_sync(0xffffffffu, s, j);
            float wj = __shfl_sync(0xffffffffu, w, j);
            float coef = wj * dd;
            float2 hs = *(const float2*)(h + (size_t)sj * 64 + lane * 2);
            acc.x = fmaf(hs.x, coef, acc.x);
            acc.y = fmaf(hs.y, coef, acc.y);
        }
    }
    *(float2*)(out + (size_t)d * 64 + lane * 2) = acc;
}

// ---------------------------------------------------------------------------
// Layer 3 GEMM: relu(in[n x 64]) @ W3[64 x 7] -> h3 only
// ---------------------------------------------------------------------------
__global__ void __launch_bounds__(256) k_gemm7(
    const float* __restrict__ in, const float* __restrict__ W,
    float* __restrict__ h_out, int n)
{
    __shared__ float wsh[64 * 7];
    int tid = threadIdx.x;
    for (int i = tid; i < 448; i += 256) wsh[i] = W[i];
    __syncthreads();

    int row = blockIdx.x * blockDim.x + tid;
    if (row >= n) return;

    float acc[7];
#pragma unroll
    for (int c = 0; c < 7; c++) acc[c] = 0.f;

    const float* p = in + (size_t)row * 64;
#pragma unroll
    for (int k = 0; k < 64; k += 4) {
        float4 v = *(const float4*)(p + k);
        v.x = fmaxf(v.x, 0.f); v.y = fmaxf(v.y, 0.f);
        v.z = fmaxf(v.z, 0.f); v.w = fmaxf(v.w, 0.f);
#pragma unroll
        for (int c = 0; c < 7; c++) {
            acc[c] = fmaf(v.x, wsh[(k + 0) * 7 + c], acc[c]);
            acc[c] = fmaf(v.y, wsh[(k + 1) * 7 + c], acc[c]);
            acc[c] = fmaf(v.z, wsh[(k + 2) * 7 + c], acc[c]);
            acc[c] = fmaf(v.w, wsh[(k + 3) * 7 + c], acc[c]);
        }
    }
#pragma unroll
    for (int c = 0; c < 7; c++)
        h_out[(size_t)row * 7 + c] = acc[c];
}

// ---------------------------------------------------------------------------
// CSR pull aggregation (7-wide)
// ---------------------------------------------------------------------------
__global__ void __launch_bounds__(256) k_agg7_csr(
    const float* __restrict__ h, const float* __restrict__ b,
    float* __restrict__ out, int n)
{
    int warp = (blockIdx.x * 256 + threadIdx.x) >> 5;
    int lane = threadIdx.x & 31;
    if (warp >= n) return;
    int d = warp;

    float dd = g_dinv[d];
    int start = g_ptr[d];
    int deg   = g_deg[d];

    float acc = 0.f;
    if (lane < 7)
        acc = fmaf(h[(size_t)d * 7 + lane], dd * dd, b[lane]);

    for (int base = 0; base < deg; base += 32) {
        int cnt = min(32, deg - base);
        int s = 0; float w = 0.f;
        if (lane < cnt) {
            s = g_csr[start + base + lane];
            w = g_dinv[s];
        }
        for (int j = 0; j < cnt; j++) {
            int   sj = __shfl_sync(0xffffffffu, s, j);
            float wj = __shfl_sync(0xffffffffu, w, j);
            if (lane < 7)
                acc = fmaf(h[(size_t)sj * 7 + lane], wj * dd, acc);
        }
    }
    if (lane < 7)
        out[(size_t)d * 7 + lane] = acc;
}

// ---------------------------------------------------------------------------
// launch — CSR build (default stream) overlapped with gemm1 (side stream)
// ---------------------------------------------------------------------------
extern "C" void kernel_launch(void* const* d_in, const int* in_sizes, int n_in,
                              void* d_out, int out_size)
{
    const float* x  = (const float*)d_in[0];
    const int*   ei = (const int*)d_in[1];
    const float* W1 = (const float*)d_in[2];
    const float* b1 = (const float*)d_in[3];
    const float* W2 = (const float*)d_in[4];
    const float* b2 = (const float*)d_in[5];
    const float* W3 = (const float*)d_in[6];
    const float* b3 = (const float*)d_in[7];

    int n  = in_sizes[0] / 128;
    int nE = in_sizes[1] / 2;
    float* out = (float*)d_out;

    float *bufA, *bufB, *h3;
    int* degp;
    cudaGetSymbolAddress((void**)&bufA, g_bufA);
    cudaGetSymbolAddress((void**)&bufB, g_bufB);
    cudaGetSymbolAddress((void**)&h3,   g_h3);
    cudaGetSymbolAddress((void**)&degp, g_deg);

    static cudaStream_t s2 = nullptr;
    static cudaEvent_t evFork = nullptr, evJoin = nullptr;
    if (!s2) {
        cudaStreamCreateWithFlags(&s2, cudaStreamNonBlocking);
        cudaEventCreateWithFlags(&evFork, cudaEventDisableTiming);
        cudaEventCreateWithFlags(&evJoin, cudaEventDisableTiming);
    }

    int nb_n = (n + 255) / 256;
    int nb_e = (nE + 255) / 256;
    int nb_g = (n + 63) / 64;
    int nb_w = (int)(((long long)n * 32 + 255) / 256);

    // fork: gemm1 on side stream (depends only on x, W1)
    cudaEventRecord(evFork, 0);
    cudaStreamWaitEvent(s2, evFork, 0);
    k_gemm64<128, false><<<nb_g, 256, 0, s2>>>(x, W1, bufA, n);
    cudaEventRecord(evJoin, s2);

    // CSR build on default stream (runs concurrently with gemm1)
    cudaMemsetAsync(degp, 0, (size_t)n * sizeof(int));
    k_count_deg<<<nb_e, 256>>>(ei, nE);
    k_scanA<<<nb_n, 256>>>(n);
    k_scanC<<<nb_n, 256>>>(n);
    k_fill<<<nb_e, 256>>>(ei, nE);

    // join: agg1 needs CSR (stream order) + gemm1 (event)
    cudaStreamWaitEvent(0, evJoin, 0);
    k_agg64_csr<<<nb_w, 256>>>(bufA, b1, bufB, n);

    // layer 2
    k_gemm64<64, true><<<nb_g, 256>>>(bufB, W2, bufA, n);
    k_agg64_csr<<<nb_w, 256>>>(bufA, b2, bufB, n);

    // layer 3
    k_gemm7<<<nb_n, 256>>>(bufB, W3, h3, n);
    k_agg7_csr<<<nb_w, 256>>>(h3, b3, out, n);
}

// round 17
// speedup vs baseline: 1.5284x; 1.0197x over previous
#include <cuda_runtime.h>
#include <cuda_fp16.h>
#include <stdint.h>

#define N_MAX 100000
#define E_MAX 800000

// Scratch (device globals; no allocation allowed in kernel_launch)
__device__ __half g_h16[(size_t)N_MAX * 64];   // pre-agg activations (fp16)
__device__ float  g_bufB[(size_t)N_MAX * 64];  // agg outputs (fp32)
__device__ float  g_h3[(size_t)N_MAX * 7];
__device__ float  g_dinv[N_MAX];
__device__ int    g_deg[N_MAX];
__device__ int    g_ptr[N_MAX];
__device__ int    g_fill[N_MAX];
__device__ int    g_csr[E_MAX];
__device__ int    g_blockSums[512];

// ---------------------------------------------------------------------------
// degree (zeroing done by cudaMemsetAsync in kernel_launch)
// ---------------------------------------------------------------------------
__global__ void k_count_deg(const int* __restrict__ ei, int nE) {
    int e = blockIdx.x * blockDim.x + threadIdx.x;
    if (e < nE) atomicAdd(&g_deg[ei[nE + e]], 1);
}

// ---------------------------------------------------------------------------
// CSR build
// ---------------------------------------------------------------------------
__global__ void k_scanA(int n) {
    __shared__ int sh[256];
    int i = blockIdx.x * 256 + threadIdx.x;
    int t = threadIdx.x;
    sh[t] = (i < n) ? g_deg[i] : 0;
    __syncthreads();
    for (int s = 128; s > 0; s >>= 1) {
        if (t < s) sh[t] += sh[t + s];
        __syncthreads();
    }
    if (t == 0) g_blockSums[blockIdx.x] = sh[0];
}

__global__ void k_scanC(int n) {
    __shared__ int sh[256];
    __shared__ int blockOff;
    int i = blockIdx.x * 256 + threadIdx.x;
    int t = threadIdx.x;

    int partial = 0;
    for (int j = t; j < blockIdx.x; j += 256) partial += g_blockSums[j];
    sh[t] = partial;
    __syncthreads();
    for (int s = 128; s > 0; s >>= 1) {
        if (t < s) sh[t] += sh[t + s];
        __syncthreads();
    }
    if (t == 0) blockOff = sh[0];
    __syncthreads();

    int v = (i < n) ? g_deg[i] : 0;
    sh[t] = v;
    __syncthreads();
    for (int off = 1; off < 256; off <<= 1) {
        int x = (t >= off) ? sh[t - off] : 0;
        __syncthreads();
        sh[t] += x;
        __syncthreads();
    }
    if (i < n) {
        int excl = sh[t] - v + blockOff;
        g_ptr[i]  = excl;
        g_fill[i] = excl;
        g_dinv[i] = rsqrtf((float)v + 1.0f);
    }
}

__global__ void k_fill(const int* __restrict__ ei, int nE) {
    int e = blockIdx.x * blockDim.x + threadIdx.x;
    if (e < nE) {
        int s = ei[e];
        int d = ei[nE + e];
        int pos = atomicAdd(&g_fill[d], 1);
        g_csr[pos] = s;
    }
}

// ---------------------------------------------------------------------------
// f32x2 helpers
// ---------------------------------------------------------------------------
__device__ __forceinline__ unsigned long long pack_dup(float v) {
    unsigned long long r;
    asm("mov.b64 %0, {%1, %1};" : "=l"(r) : "f"(v));
    return r;
}
__device__ __forceinline__ void ffma2(unsigned long long& acc,
                                      unsigned long long a,
                                      unsigned long long b) {
    asm("fma.rn.f32x2 %0, %1, %2, %0;" : "+l"(acc) : "l"(a), "l"(b));
}

// ---------------------------------------------------------------------------
// GEMM (proven shape + xs XOR swizzle): [n x K] @ [K x 64] -> h_out (fp16)
// ---------------------------------------------------------------------------
template <int K, bool RELU>
__global__ void __launch_bounds__(256) k_gemm64(
    const float* __restrict__ in, const float* __restrict__ W,
    __half* __restrict__ h_out, int n)
{
    constexpr int KC = 32;
    __shared__ float xs[KC][72];
    __shared__ float ws[KC][64];

    int tid = threadIdx.x;
    int tx = tid & 15, ty = tid >> 4;
    int rowBase = blockIdx.x * 64;
    int r0 = ty * 4, c0 = tx * 4;

    unsigned long long acc2[4][2];
#pragma unroll
    for (int i = 0; i < 4; i++) { acc2[i][0] = 0ull; acc2[i][1] = 0ull; }

    int lr = tid >> 2;
    int lk = (tid & 3) * 8;

    for (int k0 = 0; k0 < K; k0 += KC) {
        {
            int grow = rowBase + lr;
            float4 v0, v1;
            if (grow < n) {
                const float* p = in + (size_t)grow * K + k0 + lk;
                v0 = *(const float4*)p;
                v1 = *(const float4*)(p + 4);
            } else {
                v0 = make_float4(0.f, 0.f, 0.f, 0.f);
                v1 = v0;
            }
            if (RELU) {
                v0.x = fmaxf(v0.x, 0.f); v0.y = fmaxf(v0.y, 0.f);
                v0.z = fmaxf(v0.z, 0.f); v0.w = fmaxf(v0.w, 0.f);
                v1.x = fmaxf(v1.x, 0.f); v1.y = fmaxf(v1.y, 0.f);
                v1.z = fmaxf(v1.z, 0.f); v1.w = fmaxf(v1.w, 0.f);
            }
            xs[lk + 0][lr ^ ((lk + 0) & 24)] = v0.x;
            xs[lk + 1][lr ^ ((lk + 1) & 24)] = v0.y;
            xs[lk + 2][lr ^ ((lk + 2) & 24)] = v0.z;
            xs[lk + 3][lr ^ ((lk + 3) & 24)] = v0.w;
            xs[lk + 4][lr ^ ((lk + 4) & 24)] = v1.x;
            xs[lk + 5][lr ^ ((lk + 5) & 24)] = v1.y;
            xs[lk + 6][lr ^ ((lk + 6) & 24)] = v1.z;
            xs[lk + 7][lr ^ ((lk + 7) & 24)] = v1.w;
        }
        {
            int lkk = tid >> 3;
            int lc  = (tid & 7) * 8;
            const float* p = W + (size_t)(k0 + lkk) * 64 + lc;
            float4 w0 = *(const float4*)p;
            float4 w1 = *(const float4*)(p + 4);
            *(float4*)&ws[lkk][lc]     = w0;
            *(float4*)&ws[lkk][lc + 4] = w1;
        }
        __syncthreads();
#pragma unroll
        for (int kk = 0; kk < KC; kk++) {
            float4 xv = *(const float4*)&xs[kk][r0 ^ (kk & 24)];
            const unsigned long long* wp =
                (const unsigned long long*)&ws[kk][c0];
            unsigned long long w0 = wp[0], w1 = wp[1];
            unsigned long long x0 = pack_dup(xv.x);
            unsigned long long x1 = pack_dup(xv.y);
            unsigned long long x2 = pack_dup(xv.z);
            unsigned long long x3 = pack_dup(xv.w);
            ffma2(acc2[0][0], x0, w0); ffma2(acc2[0][1], x0, w1);
            ffma2(acc2[1][0], x1, w0); ffma2(acc2[1][1], x1, w1);
            ffma2(acc2[2][0], x2, w0); ffma2(acc2[2][1], x2, w1);
            ffma2(acc2[3][0], x3, w0); ffma2(acc2[3][1], x3, w1);
        }
        __syncthreads();
    }

#pragma unroll
    for (int i = 0; i < 4; i++) {
        int grow = rowBase + r0 + i;
        if (grow < n) {
            float4 hv;
            hv.x = __uint_as_float((unsigned)(acc2[i][0] & 0xffffffffull));
            hv.y = __uint_as_float((unsigned)(acc2[i][0] >> 32));
            hv.z = __uint_as_float((unsigned)(acc2[i][1] & 0xffffffffull));
            hv.w = __uint_as_float((unsigned)(acc2[i][1] >> 32));
            __half2 p0 = __floats2half2_rn(hv.x, hv.y);
            __half2 p1 = __floats2half2_rn(hv.z, hv.w);
            uint2 st;
            st.x = *(unsigned*)&p0;
            st.y = *(unsigned*)&p1;
            *(uint2*)&h_out[(size_t)grow * 64 + c0] = st;
        }
    }
}

// ---------------------------------------------------------------------------
// CSR pull aggregation (64-wide): one warp per dst node; fp16 gathers,
// fp32 math.  out[d] = b + h[d]*dinv[d]^2 + sum h[s]*dinv[s]*dinv[d]
// ---------------------------------------------------------------------------
__global__ void __launch_bounds__(256) k_agg64_csr(
    const __half* __restrict__ h, const float* __restrict__ b,
    float* __restrict__ out, int n)
{
    int warp = (blockIdx.x * 256 + threadIdx.x) >> 5;
    int lane = threadIdx.x & 31;
    if (warp >= n) return;
    int d = warp;

    float dd = g_dinv[d];
    int start = g_ptr[d];
    int deg   = g_deg[d];

    float2 hv = __half22float2(
        *(const __half2*)(h + (size_t)d * 64 + lane * 2));
    float d2 = dd * dd;
    float2 acc;
    acc.x = fmaf(hv.x, d2, b[lane * 2]);
    acc.y = fmaf(hv.y, d2, b[lane * 2 + 1]);

    for (int base = 0; base < deg; base += 32) {
        int cnt = min(32, deg - base);
        int s = 0; float w = 0.f;
        if (lane < cnt) {
            s = g_csr[start + base + lane];
            w = g_dinv[s];
        }
#pragma unroll 4
        for (int j = 0; j < cnt; j++) {
            int   sj = __shfl_sync(0xffffffffu, s, j);
            float wj = __shfl_sync(0xffffffffu, w, j);
            float coef = wj * dd;
            float2 hs = __half22float2(
                *(const __half2*)(h + (size_t)sj * 64 + lane * 2));
            acc.x = fmaf(hs.x, coef, acc.x);
            acc.y = fmaf(hs.y, coef, acc.y);
        }
    }
    *(float2*)(out + (size_t)d * 64 + lane * 2) = acc;
}

// ---------------------------------------------------------------------------
// Layer 3 GEMM: relu(in[n x 64]) @ W3[64 x 7] -> h3 only (fp32)
// ---------------------------------------------------------------------------
__global__ void __launch_bounds__(256) k_gemm7(
    const float* __restrict__ in, const float* __restrict__ W,
    float* __restrict__ h_out, int n)
{
    __shared__ float wsh[64 * 7];
    int tid = threadIdx.x;
    for (int i = tid; i < 448; i += 256) wsh[i] = W[i];
    __syncthreads();

    int row = blockIdx.x * blockDim.x + tid;
    if (row >= n) return;

    float acc[7];
#pragma unroll
    for (int c = 0; c < 7; c++) acc[c] = 0.f;

    const float* p = in + (size_t)row * 64;
#pragma unroll
    for (int k = 0; k < 64; k += 4) {
        float4 v = *(const float4*)(p + k);
        v.x = fmaxf(v.x, 0.f); v.y = fmaxf(v.y, 0.f);
        v.z = fmaxf(v.z, 0.f); v.w = fmaxf(v.w, 0.f);
#pragma unroll
        for (int c = 0; c < 7; c++) {
            acc[c] = fmaf(v.x, wsh[(k + 0) * 7 + c], acc[c]);
            acc[c] = fmaf(v.y, wsh[(k + 1) * 7 + c], acc[c]);
            acc[c] = fmaf(v.z, wsh[(k + 2) * 7 + c], acc[c]);
            acc[c] = fmaf(v.w, wsh[(k + 3) * 7 + c], acc[c]);
        }
    }
#pragma unroll
    for (int c = 0; c < 7; c++)
        h_out[(size_t)row * 7 + c] = acc[c];
}

// ---------------------------------------------------------------------------
// CSR pull aggregation (7-wide, fp32)
// ---------------------------------------------------------------------------
__global__ void __launch_bounds__(256) k_agg7_csr(
    const float* __restrict__ h, const float* __restrict__ b,
    float* __restrict__ out, int n)
{
    int warp = (blockIdx.x * 256 + threadIdx.x) >> 5;
    int lane = threadIdx.x & 31;
    if (warp >= n) return;
    int d = warp;

    float dd = g_dinv[d];
    int start = g_ptr[d];
    int deg   = g_deg[d];

    float acc = 0.f;
    if (lane < 7)
        acc = fmaf(h[(size_t)d * 7 + lane], dd * dd, b[lane]);

    for (int base = 0; base < deg; base += 32) {
        int cnt = min(32, deg - base);
        int s = 0; float w = 0.f;
        if (lane < cnt) {
            s = g_csr[start + base + lane];
            w = g_dinv[s];
        }
        for (int j = 0; j < cnt; j++) {
            int   sj = __shfl_sync(0xffffffffu, s, j);
            float wj = __shfl_sync(0xffffffffu, w, j);
            if (lane < 7)
                acc = fmaf(h[(size_t)sj * 7 + lane], wj * dd, acc);
        }
    }
    if (lane < 7)
        out[(size_t)d * 7 + lane] = acc;
}

// ---------------------------------------------------------------------------
// launch — CSR build (default stream) overlapped with gemm1 (side stream)
// ---------------------------------------------------------------------------
extern "C" void kernel_launch(void* const* d_in, const int* in_sizes, int n_in,
                              void* d_out, int out_size)
{
    const float* x  = (const float*)d_in[0];
    const int*   ei = (const int*)d_in[1];
    const float* W1 = (const float*)d_in[2];
    const float* b1 = (const float*)d_in[3];
    const float* W2 = (const float*)d_in[4];
    const float* b2 = (const float*)d_in[5];
    const float* W3 = (const float*)d_in[6];
    const float* b3 = (const float*)d_in[7];

    int n  = in_sizes[0] / 128;
    int nE = in_sizes[1] / 2;
    float* out = (float*)d_out;

    __half* h16;
    float *bufB, *h3;
    int* degp;
    cudaGetSymbolAddress((void**)&h16,  g_h16);
    cudaGetSymbolAddress((void**)&bufB, g_bufB);
    cudaGetSymbolAddress((void**)&h3,   g_h3);
    cudaGetSymbolAddress((void**)&degp, g_deg);

    static cudaStream_t s2 = nullptr;
    static cudaEvent_t evFork = nullptr, evJoin = nullptr;
    if (!s2) {
        cudaStreamCreateWithFlags(&s2, cudaStreamNonBlocking);
        cudaEventCreateWithFlags(&evFork, cudaEventDisableTiming);
        cudaEventCreateWithFlags(&evJoin, cudaEventDisableTiming);
    }

    int nb_n = (n + 255) / 256;
    int nb_e = (nE + 255) / 256;
    int nb_g = (n + 63) / 64;
    int nb_w = (int)(((long long)n * 32 + 255) / 256);

    // fork: gemm1 on side stream (depends only on x, W1)
    cudaEventRecord(evFork, 0);
    cudaStreamWaitEvent(s2, evFork, 0);
    k_gemm64<128, false><<<nb_g, 256, 0, s2>>>(x, W1, h16, n);
    cudaEventRecord(evJoin, s2);

    // CSR build on default stream (runs concurrently with gemm1)
    cudaMemsetAsync(degp, 0, (size_t)n * sizeof(int));
    k_count_deg<<<nb_e, 256>>>(ei, nE);
    k_scanA<<<nb_n, 256>>>(n);
    k_scanC<<<nb_n, 256>>>(n);
    k_fill<<<nb_e, 256>>>(ei, nE);

    // join: agg1 needs CSR (stream order) + gemm1 (event)
    cudaStreamWaitEvent(0, evJoin, 0);
    k_agg64_csr<<<nb_w, 256>>>(h16, b1, bufB, n);

    // layer 2
    k_gemm64<64, true><<<nb_g, 256>>>(bufB, W2, h16, n);
    k_agg64_csr<<<nb_w, 256>>>(h16, b2, bufB, n);

    // layer 3
    k_gemm7<<<nb_n, 256>>>(bufB, W3, h3, n);
    k_agg7_csr<<<nb_w, 256>>>(h3, b3, out, n);
}